// round 4
// baseline (speedup 1.0000x reference)
#include <cuda_runtime.h>
#include <math.h>
#include <stdint.h>

// Problem shape (fixed by the benchmark reference)
#define NB 4
#define NG 1024
#define NT 1024
#define NK 5
#define NC 8

// Tiling
#define G_SPLIT 4
#define GH (NG / G_SPLIT)      // 256 g's staged per CTA
#define T_TILE 28              // 37*28 = 1036 >= 1024
#define N_TTILES 37
#define TLH 14                 // t-lanes; each thread owns t and t+TLH
#define BLOCK (TLH * NC)       // 112 threads
#define HROW (NK * NC)         // 40

// smem (floats): uv (float2 per (g,c)) | hA (k0,k1) | hB (k2,k3) | hC (k4)
#define UV_F (GH * NC * 2)     // 4096
#define HA_F (GH * NC * 2)     // 4096
#define HB_F (GH * NC * 2)     // 4096
#define HC_F (GH * NC)         // 2048
#define SMEM_FLOATS (UV_F + HA_F + HB_F + HC_F)   // 14336 floats = 57344 B -> 4 CTAs/SM

#define NEG_HALF_LOG2E -0.72134752044448170f      // -0.5 * log2(e)

__device__ __forceinline__ float ex2f(float x) {
    float r; asm("ex2.approx.ftz.f32 %0, %1;" : "=f"(r) : "f"(x)); return r;
}
__device__ __forceinline__ uint64_t pack2(float lo, float hi) {
    uint64_t r; asm("mov.b64 %0, {%1, %2};" : "=l"(r) : "f"(lo), "f"(hi)); return r;
}
__device__ __forceinline__ void unpack2(uint64_t v, float& lo, float& hi) {
    asm("mov.b64 {%0, %1}, %2;" : "=f"(lo), "=f"(hi) : "l"(v));
}
__device__ __forceinline__ uint64_t fma2(uint64_t a, uint64_t b, uint64_t c) {
    uint64_t d;
    asm("fma.rn.f32x2 %0, %1, %2, %3;" : "=l"(d) : "l"(a), "l"(b), "l"(c));
    return d;
}

__global__ void zero_out_kernel(float* __restrict__ out, int n) {
    int i = blockIdx.x * blockDim.x + threadIdx.x;
    if (i < n) out[i] = 0.0f;
}

__global__ __launch_bounds__(BLOCK) void gauss_kernel(
    const float* __restrict__ x_grid,   // (b, g, c)
    const float* __restrict__ h_grid,   // (b, g, k, c)
    const float* __restrict__ target_x, // (b, t, c)
    const float* __restrict__ sigma,    // (k, c)
    float* __restrict__ out)            // (b, t, k, c)
{
    extern __shared__ float sm[];
    float* uv = sm;                 // float2[(g,c)] = {u = m0*x^2, w = -2*m0*x}
    float* ha = uv + UV_F;          // float2[(g,c)] = {h_k0, h_k1}
    float* hb = ha + HA_F;          // float2[(g,c)] = {h_k2, h_k3}
    float* hc = hb + HB_F;          // float [(g,c)] =  h_k4

    const int gh   = blockIdx.x;    // g quarter
    const int tile = blockIdx.y;    // t tile
    const int b    = blockIdx.z;    // batch
    const int tid  = threadIdx.x;
    const int c    = tid & (NC - 1);
    const int tl   = tid >> 3;

    // Per-thread exponent multipliers from sigma (base-2; matches exp(sigma)+EPS)
    float mk[NK];
    bool uni = true;
    #pragma unroll
    for (int k = 0; k < NK; ++k) {
        float s = expf(sigma[k * NC + c]) + 1e-6f;
        mk[k] = NEG_HALF_LOG2E / (s * s);
        if (k > 0) uni = uni && (mk[k] == mk[0]);
    }
    const float m0 = mk[0];

    // ---- Stage x -> (u, w). Note: i & 7 == c for all iterations (BLOCK % 8 == 0).
    {
        const float* xg = x_grid + ((size_t)b * NG + (size_t)gh * GH) * NC;
        for (int i = tid; i < GH * NC; i += BLOCK) {
            float x = xg[i];
            float u = m0 * x * x;
            float w = -2.0f * m0 * x;
            *(float2*)(uv + 2 * i) = make_float2(u, w);
        }
    }
    // ---- Stage h with k-split transpose: global [g][k][c] -> hA/hB/hC by (g,c)
    {
        const float4* hg4 = (const float4*)(h_grid + ((size_t)b * NG + (size_t)gh * GH) * HROW);
        for (int i4 = tid; i4 < GH * HROW / 4; i4 += BLOCK) {
            float4 v = hg4[i4];
            int e0 = i4 * 4;
            float vv[4] = {v.x, v.y, v.z, v.w};
            #pragma unroll
            for (int j = 0; j < 4; ++j) {
                int e = e0 + j;
                int g = e / HROW;
                int rem = e - g * HROW;
                int k = rem >> 3;
                int cc = rem & 7;
                int gc = g * NC + cc;
                float val = vv[j];
                if (k < 2)      ha[gc * 2 + k] = val;
                else if (k < 4) hb[gc * 2 + (k - 2)] = val;
                else            hc[gc] = val;
            }
        }
    }
    __syncthreads();

    const int t0 = tile * T_TILE + tl;
    const int t1 = t0 + TLH;
    float y0 = 0.0f, y1 = 0.0f;
    if (t0 < NT) y0 = target_x[((size_t)b * NT + t0) * NC + c];
    if (t1 < NT) y1 = target_x[((size_t)b * NT + t1) * NC + c];

    const float2* uvc = (const float2*)uv + c;
    const float2* hac = (const float2*)ha + c;
    const float2* hbc = (const float2*)hb + c;
    const float*  hcc = hc + c;

    if (uni) {
        // Fast path: arg = u + w*y (per t), one ex2 serves all 5 k's,
        // k-pairs accumulated with packed f32x2 FMA; 2^(m0*y^2) factored out.
        uint64_t acc0a = 0, acc0b = 0, acc1a = 0, acc1b = 0;
        float acc0c = 0.0f, acc1c = 0.0f;
        #pragma unroll 4
        for (int g = 0; g < GH; ++g) {
            float2 uw = uvc[g * NC];
            float a0 = fmaf(uw.y, y0, uw.x);
            float a1 = fmaf(uw.y, y1, uw.x);
            float e0 = ex2f(a0);
            float e1 = ex2f(a1);
            float2 hA = hac[g * NC];
            float2 hB = hbc[g * NC];
            float  hC = hcc[g * NC];
            acc0c = fmaf(e0, hC, acc0c);
            acc1c = fmaf(e1, hC, acc1c);
            uint64_t hAp = pack2(hA.x, hA.y);
            uint64_t hBp = pack2(hB.x, hB.y);
            uint64_t e0p = pack2(e0, e0);
            uint64_t e1p = pack2(e1, e1);
            acc0a = fma2(e0p, hAp, acc0a);
            acc0b = fma2(e0p, hBp, acc0b);
            acc1a = fma2(e1p, hAp, acc1a);
            acc1b = fma2(e1p, hBp, acc1b);
        }
        float s0 = ex2f(m0 * y0 * y0);
        float s1 = ex2f(m0 * y1 * y1);
        if (t0 < NT) {
            float* o = out + ((size_t)b * NT + t0) * HROW + c;
            float v0, v1;
            unpack2(acc0a, v0, v1);
            atomicAdd(o + 0 * NC, v0 * s0);
            atomicAdd(o + 1 * NC, v1 * s0);
            unpack2(acc0b, v0, v1);
            atomicAdd(o + 2 * NC, v0 * s0);
            atomicAdd(o + 3 * NC, v1 * s0);
            atomicAdd(o + 4 * NC, acc0c * s0);
        }
        if (t1 < NT) {
            float* o = out + ((size_t)b * NT + t1) * HROW + c;
            float v0, v1;
            unpack2(acc1a, v0, v1);
            atomicAdd(o + 0 * NC, v0 * s1);
            atomicAdd(o + 1 * NC, v1 * s1);
            unpack2(acc1b, v0, v1);
            atomicAdd(o + 2 * NC, v0 * s1);
            atomicAdd(o + 3 * NC, v1 * s1);
            atomicAdd(o + 4 * NC, acc1c * s1);
        }
    } else {
        // General path: per-k scales. Recover (x-y)^2 from (u,w), rescale per k.
        float ac0[NK], ac1[NK];
        #pragma unroll
        for (int k = 0; k < NK; ++k) { ac0[k] = 0.0f; ac1[k] = 0.0f; }
        const float inv_m0 = 1.0f / m0;
        const float r0 = m0 * y0 * y0;
        const float r1 = m0 * y1 * y1;
        #pragma unroll 2
        for (int g = 0; g < GH; ++g) {
            float2 uw = uvc[g * NC];
            float d20 = (fmaf(uw.y, y0, uw.x) + r0) * inv_m0;   // (x-y0)^2
            float d21 = (fmaf(uw.y, y1, uw.x) + r1) * inv_m0;
            float2 hA = hac[g * NC];
            float2 hB = hbc[g * NC];
            float  hC = hcc[g * NC];
            float h[NK] = {hA.x, hA.y, hB.x, hB.y, hC};
            #pragma unroll
            for (int k = 0; k < NK; ++k) {
                ac0[k] = fmaf(ex2f(d20 * mk[k]), h[k], ac0[k]);
                ac1[k] = fmaf(ex2f(d21 * mk[k]), h[k], ac1[k]);
            }
        }
        if (t0 < NT) {
            float* o = out + ((size_t)b * NT + t0) * HROW + c;
            #pragma unroll
            for (int k = 0; k < NK; ++k) atomicAdd(o + k * NC, ac0[k]);
        }
        if (t1 < NT) {
            float* o = out + ((size_t)b * NT + t1) * HROW + c;
            #pragma unroll
            for (int k = 0; k < NK; ++k) atomicAdd(o + k * NC, ac1[k]);
        }
    }
}

extern "C" void kernel_launch(void* const* d_in, const int* in_sizes, int n_in,
                              void* d_out, int out_size) {
    const float* x_grid  = (const float*)d_in[0];
    const float* h_grid  = (const float*)d_in[1];
    const float* target  = (const float*)d_in[2];
    const float* sigma   = (const float*)d_in[3];
    float* out = (float*)d_out;

    size_t smem = SMEM_FLOATS * sizeof(float);   // 57344 B -> 4 CTAs/SM
    cudaFuncSetAttribute(gauss_kernel, cudaFuncAttributeMaxDynamicSharedMemorySize, (int)smem);

    zero_out_kernel<<<(out_size + 255) / 256, 256>>>(out, out_size);

    dim3 grid(G_SPLIT, N_TTILES, NB);   // 4 x 37 x 4 = 592 = 148 SMs * 4 CTAs
    gauss_kernel<<<grid, BLOCK, smem>>>(x_grid, h_grid, target, sigma, out);
}

// round 5
// speedup vs baseline: 1.5920x; 1.5920x over previous
#include <cuda_runtime.h>
#include <math.h>

// Problem shape (fixed by the benchmark reference)
#define NB 4
#define NG 1024
#define NT 1024
#define NK 5
#define NC 8
#define HROW (NK * NC)         // 40

// Tiling: 16 t-lanes x 8 channels = 128 threads; each thread owns 4 t's.
#define BLOCK 128
#define TL 16                  // t-lanes
#define T_TILE 64              // 4 t's per lane * 16 lanes
#define N_TTILES 16            // 16 * 64 = 1024 exactly, no waste
#define G_SPLIT 8
#define GH (NG / G_SPLIT)      // 128 g's staged per CTA

// smem: uw (float2 per (g,c)) + h natural layout
#define UW_F (2 * GH * NC)     // 2048 floats
#define H_F  (GH * HROW)       // 5120 floats
#define SMEM_BYTES ((UW_F + H_F) * 4)   // 28672 B

#define NEG_HALF_LOG2E -0.72134752044448170f   // -0.5 * log2(e)

__device__ __forceinline__ float ex2f(float x) {
    float r; asm("ex2.approx.ftz.f32 %0, %1;" : "=f"(r) : "f"(x)); return r;
}

__global__ __launch_bounds__(BLOCK) void gauss_kernel(
    const float* __restrict__ x_grid,   // (b, g, c)
    const float* __restrict__ h_grid,   // (b, g, k, c)
    const float* __restrict__ target_x, // (b, t, c)
    const float* __restrict__ sigma,    // (k, c)
    float* __restrict__ out)            // (b, t, k, c)
{
    extern __shared__ float sm[];
    float* uw = sm;             // float2[(g,c)] = {u = m0*x^2, w = -2*m0*x}
    float* hs = uw + UW_F;      // h natural [g][k][c]

    const int gh   = blockIdx.x;    // g slice
    const int tile = blockIdx.y;    // t tile
    const int b    = blockIdx.z;    // batch
    const int tid  = threadIdx.x;
    const int c    = tid & (NC - 1);
    const int tl   = tid >> 3;

    // Per-channel exponent multipliers from sigma (base-2; matches exp(sigma)+EPS)
    float mk[NK];
    bool uni = true;
    #pragma unroll
    for (int k = 0; k < NK; ++k) {
        float s = expf(sigma[k * NC + c]) + 1e-6f;
        mk[k] = NEG_HALF_LOG2E / (s * s);
        if (k > 0) uni = uni && (mk[k] == mk[0]);
    }
    const float m0 = mk[0];

    // ---- Stage x -> (u, w). BLOCK % NC == 0 so (tid + r*BLOCK) & 7 == c always:
    // each thread transforms elements of its own channel with its own m0.
    {
        const float* xg = x_grid + ((size_t)b * NG + (size_t)gh * GH) * NC;
        #pragma unroll
        for (int r = 0; r < GH * NC / BLOCK; ++r) {       // 8 exact iters
            int i = tid + r * BLOCK;
            float x = xg[i];
            *(float2*)(uw + 2 * i) = make_float2(m0 * x * x, -2.0f * m0 * x);
        }
    }
    // ---- Stage h: straight float4 copy, natural layout, no index math.
    {
        const float4* hg4 = (const float4*)(h_grid + ((size_t)b * NG + (size_t)gh * GH) * HROW);
        float4* hs4 = (float4*)hs;
        #pragma unroll
        for (int r = 0; r < H_F / 4 / BLOCK; ++r) {       // 10 exact iters
            int i = tid + r * BLOCK;
            hs4[i] = hg4[i];
        }
    }
    __syncthreads();

    // 4 t's per thread: t = tile*64 + tl + {0,16,32,48}; always < 1024.
    const int tbase = tile * T_TILE + tl;
    const float* ty = target_x + ((size_t)b * NT + tbase) * NC + c;
    const float y0 = ty[0 * TL * NC];
    const float y1 = ty[1 * TL * NC];
    const float y2 = ty[2 * TL * NC];
    const float y3 = ty[3 * TL * NC];

    float a0[NK] = {0,0,0,0,0};
    float a1[NK] = {0,0,0,0,0};
    float a2[NK] = {0,0,0,0,0};
    float a3[NK] = {0,0,0,0,0};

    const float2* uwc = (const float2*)uw + c;
    const float*  hc  = hs + c;

    if (uni) {
        // Fast path: 1 ex2 serves all 5 k's; 2^(m0*y^2) factored out of the g-sum.
        #pragma unroll 2
        for (int g = 0; g < GH; ++g) {
            float2 p = uwc[g * NC];
            float e0 = ex2f(fmaf(p.y, y0, p.x));
            float e1 = ex2f(fmaf(p.y, y1, p.x));
            float e2 = ex2f(fmaf(p.y, y2, p.x));
            float e3 = ex2f(fmaf(p.y, y3, p.x));
            const float* hp = hc + g * HROW;
            #pragma unroll
            for (int k = 0; k < NK; ++k) {
                float h = hp[k * NC];
                a0[k] = fmaf(e0, h, a0[k]);
                a1[k] = fmaf(e1, h, a1[k]);
                a2[k] = fmaf(e2, h, a2[k]);
                a3[k] = fmaf(e3, h, a3[k]);
            }
        }
        const float s0 = ex2f(m0 * y0 * y0);
        const float s1 = ex2f(m0 * y1 * y1);
        const float s2 = ex2f(m0 * y2 * y2);
        const float s3 = ex2f(m0 * y3 * y3);
        float* o = out + ((size_t)b * NT + tbase) * HROW + c;
        #pragma unroll
        for (int k = 0; k < NK; ++k) {
            atomicAdd(o + 0 * TL * HROW + k * NC, a0[k] * s0);
            atomicAdd(o + 1 * TL * HROW + k * NC, a1[k] * s1);
            atomicAdd(o + 2 * TL * HROW + k * NC, a2[k] * s2);
            atomicAdd(o + 3 * TL * HROW + k * NC, a3[k] * s3);
        }
    } else {
        // General path: per-k scales. q = m0*(x-y)^2 recovered via +m0*y^2; rescale by mk/m0.
        float rk[NK];
        #pragma unroll
        for (int k = 0; k < NK; ++k) rk[k] = mk[k] / m0;
        const float r0 = m0 * y0 * y0;
        const float r1 = m0 * y1 * y1;
        const float r2 = m0 * y2 * y2;
        const float r3 = m0 * y3 * y3;
        for (int g = 0; g < GH; ++g) {
            float2 p = uwc[g * NC];
            float q0 = fmaf(p.y, y0, p.x) + r0;
            float q1 = fmaf(p.y, y1, p.x) + r1;
            float q2 = fmaf(p.y, y2, p.x) + r2;
            float q3 = fmaf(p.y, y3, p.x) + r3;
            const float* hp = hc + g * HROW;
            #pragma unroll
            for (int k = 0; k < NK; ++k) {
                float h = hp[k * NC];
                a0[k] = fmaf(ex2f(q0 * rk[k]), h, a0[k]);
                a1[k] = fmaf(ex2f(q1 * rk[k]), h, a1[k]);
                a2[k] = fmaf(ex2f(q2 * rk[k]), h, a2[k]);
                a3[k] = fmaf(ex2f(q3 * rk[k]), h, a3[k]);
            }
        }
        float* o = out + ((size_t)b * NT + tbase) * HROW + c;
        #pragma unroll
        for (int k = 0; k < NK; ++k) {
            atomicAdd(o + 0 * TL * HROW + k * NC, a0[k]);
            atomicAdd(o + 1 * TL * HROW + k * NC, a1[k]);
            atomicAdd(o + 2 * TL * HROW + k * NC, a2[k]);
            atomicAdd(o + 3 * TL * HROW + k * NC, a3[k]);
        }
    }
}

extern "C" void kernel_launch(void* const* d_in, const int* in_sizes, int n_in,
                              void* d_out, int out_size) {
    const float* x_grid  = (const float*)d_in[0];
    const float* h_grid  = (const float*)d_in[1];
    const float* target  = (const float*)d_in[2];
    const float* sigma   = (const float*)d_in[3];
    float* out = (float*)d_out;

    cudaFuncSetAttribute(gauss_kernel, cudaFuncAttributeMaxDynamicSharedMemorySize, SMEM_BYTES);

    cudaMemsetAsync(out, 0, (size_t)out_size * sizeof(float), 0);

    dim3 grid(G_SPLIT, N_TTILES, NB);   // 8 x 16 x 4 = 512 CTAs, all resident in one wave
    gauss_kernel<<<grid, BLOCK, SMEM_BYTES>>>(x_grid, h_grid, target, sigma, out);
}